// round 15
// baseline (speedup 1.0000x reference)
#include <cuda_runtime.h>
#include <cuda_bf16.h>
#include <math.h>
#include <cstdint>

#define BN 8192
#define CN 1000
#define CPAD 1024
#define DN 128
#define TSPLIT 8
#define STRIDE 272                 // bytes per tile row: 256 data + 16 pad (conflict-free ldmatrix)
#define TILE_BYTES (128 * STRIDE)  // 34816
#define SMEM_NSD (2 * TILE_BYTES + 512)
#define SMEM_SCL (TILE_BYTES + 512)

// ---------------- scratch ---------------------------------------------------
__device__ float g_featn[BN * DN];
__device__ __nv_bfloat16 g_featbH[BN * DN];
__device__ __nv_bfloat16 g_featbL[BN * DN];
__device__ float g_meansn[CN * DN];
__device__ __nv_bfloat16 g_meansBH[CPAD * DN];
__device__ __nv_bfloat16 g_meansBL[CPAD * DN];
__device__ float g_XX[BN];
__device__ float g_YY[CN];
__device__ int   g_lab[BN];
__device__ float g_pb[TSPLIT * BN];    // bottom partials (self included; removed in combine)
__device__ float g_S[CN * DN];         // class feature sums
__device__ int   g_cnt[CN];            // class counts
__device__ float g_ce[BN];
__device__ float g_margin[BN];
__device__ float g_peri[BN];
__device__ float g_valid[BN];

__device__ __forceinline__ uint32_t smem_u32(const void* p) {
    uint32_t a;
    asm("{ .reg .u64 t; cvta.to.shared.u64 t, %1; cvt.u32.u64 %0, t; }" : "=r"(a) : "l"(p));
    return a;
}
__device__ __forceinline__ void bf16_split(float x, __nv_bfloat16& hi, __nv_bfloat16& lo) {
    hi = __float2bfloat16(x);
    lo = __float2bfloat16(x - __bfloat162float(hi));
}

#define HMMA4(ACC, A, B0, B1) \
    asm("mma.sync.aligned.m16n8k16.row.col.f32.bf16.bf16.f32 " \
        "{%0,%1,%2,%3}, {%4,%5,%6,%7}, {%8,%9}, {%0,%1,%2,%3};" \
        : "+f"((ACC)[0]), "+f"((ACC)[1]), "+f"((ACC)[2]), "+f"((ACC)[3]) \
        : "r"((A)[0]), "r"((A)[1]), "r"((A)[2]), "r"((A)[3]), "r"(B0), "r"(B1))

#define LDSM4(R, ADDR) \
    asm volatile("ldmatrix.sync.aligned.m8n8.x4.shared.b16 {%0,%1,%2,%3}, [%4];" \
                 : "=r"((R)[0]), "=r"((R)[1]), "=r"((R)[2]), "=r"((R)[3]) : "r"(ADDR))

// ---------------- prep -------------------------------------------------------
__global__ void prep_feat_kernel(const float* __restrict__ feat,
                                 const int* __restrict__ labels) {
    int row = blockIdx.x * 8 + threadIdx.y;
    int lane = threadIdx.x;
    float4 v = ((const float4*)(feat + (size_t)row * DN))[lane];
    float ss = v.x * v.x + v.y * v.y + v.z * v.z + v.w * v.w;
    #pragma unroll
    for (int d = 16; d; d >>= 1) ss += __shfl_xor_sync(0xffffffffu, ss, d);
    float inv = 1.0f / fmaxf(sqrtf(ss), 1e-12f);
    float4 o = make_float4(v.x * inv, v.y * inv, v.z * inv, v.w * inv);
    ((float4*)(g_featn + (size_t)row * DN))[lane] = o;

    __nv_bfloat16 hx, lx, hy, ly, hz, lz, hw, lw;
    bf16_split(o.x, hx, lx); bf16_split(o.y, hy, ly);
    bf16_split(o.z, hz, lz); bf16_split(o.w, hw, lw);
    __nv_bfloat162 h0 = __nv_bfloat162(hx, hy), h1 = __nv_bfloat162(hz, hw);
    __nv_bfloat162 l0 = __nv_bfloat162(lx, ly), l1 = __nv_bfloat162(lz, lw);
    ((uint2*)(g_featbH + (size_t)row * DN))[lane] = make_uint2(*(uint32_t*)&h0, *(uint32_t*)&h1);
    ((uint2*)(g_featbL + (size_t)row * DN))[lane] = make_uint2(*(uint32_t*)&l0, *(uint32_t*)&l1);
    if (lane == 0) {
        g_XX[row] = ss * inv * inv;
        g_lab[row] = labels[row];
    }
}

__global__ void prep_means_kernel(const float* __restrict__ means) {
    int row = blockIdx.x * 8 + threadIdx.y;   // 128 blocks * 8 = 1024 (padded)
    int lane = threadIdx.x;
    float4 v = make_float4(0.f, 0.f, 0.f, 0.f);
    if (row < CN) v = ((const float4*)(means + (size_t)row * DN))[lane];
    float ss = v.x * v.x + v.y * v.y + v.z * v.z + v.w * v.w;
    #pragma unroll
    for (int d = 16; d; d >>= 1) ss += __shfl_xor_sync(0xffffffffu, ss, d);
    float inv = 1.0f / fmaxf(sqrtf(ss), 1e-12f);

    __nv_bfloat16 hx, lx, hy, ly, hz, lz, hw, lw;
    bf16_split(v.x, hx, lx); bf16_split(v.y, hy, ly);
    bf16_split(v.z, hz, lz); bf16_split(v.w, hw, lw);
    __nv_bfloat162 h0 = __nv_bfloat162(hx, hy), h1 = __nv_bfloat162(hz, hw);
    __nv_bfloat162 l0 = __nv_bfloat162(lx, ly), l1 = __nv_bfloat162(lz, lw);
    ((uint2*)(g_meansBH + (size_t)row * DN))[lane] = make_uint2(*(uint32_t*)&h0, *(uint32_t*)&h1);
    ((uint2*)(g_meansBL + (size_t)row * DN))[lane] = make_uint2(*(uint32_t*)&l0, *(uint32_t*)&l1);

    if (row < CN) {
        float4 o = make_float4(v.x * inv, v.y * inv, v.z * inv, v.w * inv);
        ((float4*)(g_meansn + (size_t)row * DN))[lane] = o;
        if (lane == 0) g_YY[row] = ss;
    }
}

// ---------------- class sums: one warp per class (deterministic) -------------
__global__ void __launch_bounds__(256) class_sum_kernel() {
    int w = threadIdx.x >> 5, l = threadIdx.x & 31;
    int c = blockIdx.x * 8 + w;
    float4 acc = make_float4(0.f, 0.f, 0.f, 0.f);
    int count = 0;
    for (int base = 0; base < BN; base += 32) {
        int lb = g_lab[base + l];
        unsigned m = __ballot_sync(0xffffffffu, lb == c);
        count += __popc(m);
        while (m) {
            int j = __ffs(m) - 1;
            m &= m - 1;
            float4 f = ((const float4*)(g_featn + (size_t)(base + j) * DN))[l];
            acc.x += f.x; acc.y += f.y; acc.z += f.z; acc.w += f.w;
        }
    }
    ((float4*)(g_S + (size_t)c * DN))[l] = acc;
    if (l == 0) g_cnt[c] = count;
}

// copy a 128-row bf16 tile into padded smem; each thread: one half-row (128 B)
__device__ __forceinline__ void load_tile(char* dst, const __nv_bfloat16* src_base,
                                          int row0, int tid) {
    int r = tid >> 1, h = tid & 1;
    const uint4* src = (const uint4*)(src_base + (size_t)(row0 + r) * DN + h * 64);
    uint4* d = (uint4*)(dst + r * STRIDE + h * 128);
    #pragma unroll
    for (int i = 0; i < 8; i++) d[i] = src[i];
}

// extract a warp's 16-row A fragments (8 k-steps) starting at tile row `row0`
__device__ __forceinline__ void load_a_frags16(uint32_t base, int row0, int l, uint32_t a[8][4]) {
    uint32_t row = row0 + (l & 15);
    uint32_t koff = 8 * (l >> 4);
    #pragma unroll
    for (int ks = 0; ks < 8; ks++) {
        uint32_t addr = base + row * STRIDE + (16 * ks + koff) * 2;
        LDSM4(a[ks], addr);
    }
}

// ---------------- nsd GEMM via split-bf16 mma.sync ---------------------------
__global__ void __launch_bounds__(256) nsd_mma_kernel(float* __restrict__ out) {
    extern __shared__ __align__(16) char sm[];
    char* smX = sm;
    char* smY = sm + TILE_BYTES;
    float* smYY = (float*)(sm + 2 * TILE_BYTES);

    int tid = threadIdx.x;
    int w = tid >> 5, l = tid & 31;
    int ib = blockIdx.x * 128;
    int cb = blockIdx.y * 128;

    load_tile(smX, g_featbH, ib, tid);
    load_tile(smY, g_featbL, ib, tid);
    __syncthreads();

    uint32_t ah[8][4], al[8][4];
    load_a_frags16(smem_u32(smX), 16 * w, l, ah);
    load_a_frags16(smem_u32(smY), 16 * w, l, al);
    __syncthreads();

    load_tile(smX, g_meansBH, cb, tid);
    load_tile(smY, g_meansBL, cb, tid);
    if (tid < 128) {
        int c = cb + tid;
        smYY[tid] = (c < CN) ? (-0.5f * g_YY[c]) : 0.f;
    }
    __syncthreads();

    int r0 = 16 * w + (l >> 2), r1 = r0 + 8;
    int i0 = ib + r0, i1 = ib + r1;
    float nx0 = -0.5f * g_XX[i0], nx1 = -0.5f * g_XX[i1];

    uint32_t baseH = smem_u32(smX), baseL = smem_u32(smY);
    uint32_t brow = (l & 7);
    uint32_t bkoff = 8 * (l >> 3);

    #pragma unroll
    for (int nb = 0; nb < 16; nb++) {
        float hh[4] = {0.f, 0.f, 0.f, 0.f};
        float lh[4] = {0.f, 0.f, 0.f, 0.f};
        float hl[4] = {0.f, 0.f, 0.f, 0.f};
        #pragma unroll
        for (int kp = 0; kp < 4; kp++) {
            uint32_t off = (nb * 8 + brow) * STRIDE + (32 * kp + bkoff) * 2;
            uint32_t bh[4], bl[4];
            LDSM4(bh, baseH + off);
            LDSM4(bl, baseL + off);
            HMMA4(hh, ah[2 * kp],     bh[0], bh[1]);
            HMMA4(lh, al[2 * kp],     bh[0], bh[1]);
            HMMA4(hl, ah[2 * kp],     bl[0], bl[1]);
            HMMA4(hh, ah[2 * kp + 1], bh[2], bh[3]);
            HMMA4(lh, al[2 * kp + 1], bh[2], bh[3]);
            HMMA4(hl, ah[2 * kp + 1], bl[2], bl[3]);
        }
        int colloc = nb * 8 + 2 * (l & 3);
        int col = cb + colloc;
        float y0 = smYY[colloc], y1 = smYY[colloc + 1];
        if (col < CN) {
            out[(size_t)i0 * CN + col] = nx0 + (hh[0] + lh[0] + hl[0]) + y0;
            out[(size_t)i1 * CN + col] = nx1 + (hh[2] + lh[2] + hl[2]) + y0;
        }
        if (col + 1 < CN) {
            out[(size_t)i0 * CN + col + 1] = nx0 + (hh[1] + lh[1] + hl[1]) + y1;
            out[(size_t)i1 * CN + col + 1] = nx1 + (hh[3] + lh[3] + hl[3]) + y1;
        }
    }
}

// ---------------- CE + margin: one warp per row ------------------------------
__global__ void __launch_bounds__(256) ce_kernel(const float* __restrict__ nsd) {
    int w = threadIdx.x >> 5, l = threadIdx.x & 31;
    int i = blockIdx.x * 8 + w;
    int lab = g_lab[i];
    const float4* row = (const float4*)(nsd + (size_t)i * CN);

    float4 v[8];
    float m = -1e30f, vlab = -1e30f;
    #pragma unroll
    for (int k = 0; k < 8; k++) {
        int idx = l + 32 * k;
        float4 x = make_float4(-1e30f, -1e30f, -1e30f, -1e30f);
        if (idx < 250) {
            x = row[idx];
            int c0 = idx * 4;
            if (lab == c0)     { x.x *= 1.5f; vlab = x.x; }
            if (lab == c0 + 1) { x.y *= 1.5f; vlab = x.y; }
            if (lab == c0 + 2) { x.z *= 1.5f; vlab = x.z; }
            if (lab == c0 + 3) { x.w *= 1.5f; vlab = x.w; }
            m = fmaxf(m, fmaxf(fmaxf(x.x, x.y), fmaxf(x.z, x.w)));
        }
        v[k] = x;
    }
    #pragma unroll
    for (int d = 16; d; d >>= 1) {
        m = fmaxf(m, __shfl_xor_sync(0xffffffffu, m, d));
        vlab = fmaxf(vlab, __shfl_xor_sync(0xffffffffu, vlab, d));
    }
    float e = 0.f;
    #pragma unroll
    for (int k = 0; k < 8; k++)
        e += __expf(v[k].x - m) + __expf(v[k].y - m)
           + __expf(v[k].z - m) + __expf(v[k].w - m);
    #pragma unroll
    for (int d = 16; d; d >>= 1) e += __shfl_xor_sync(0xffffffffu, e, d);
    if (l == 0) g_ce[i] = -(vlab - m - logf(e));

    float4 f  = ((const float4*)(g_featn  + (size_t)i   * DN))[l];
    float4 mm = ((const float4*)(g_meansn + (size_t)lab * DN))[l];
    float dx = f.x - mm.x, dy = f.y - mm.y, dz = f.z - mm.z, dw = f.w - mm.w;
    float ms = dx * dx + dy * dy + dz * dz + dw * dw;
    #pragma unroll
    for (int d = 16; d; d >>= 1) ms += __shfl_xor_sync(0xffffffffu, ms, d);
    if (l == 0) g_margin[i] = ms;
}

// ---------------- SCL: bottom-only, mask-free fused GEMM + row reduction -----
// CTA = 256 i-rows x 128 j-cols; 8 warps x 32 rows -> 4 HMMA per B LDSM.x4.
// Self-term included here; combine subtracts exp(f_i.f_i/T).
__global__ void __launch_bounds__(256, 2) scl_mma_kernel() {
    extern __shared__ __align__(16) char sm[];
    char* smT = sm;

    int tid = threadIdx.x;
    int w = tid >> 5;
    int l = tid & 31;
    int ib = blockIdx.x * 256;
    int split = blockIdx.y;

    uint32_t a[2][8][4];   // [strip 0/1][k-step][frag]

    // half 0 (rows ib..ib+127): warps 0-3 extract their 2 strips
    load_tile(smT, g_featbH, ib, tid);
    __syncthreads();
    if (w < 4) {
        uint32_t base = smem_u32(smT);
        load_a_frags16(base, 32 * w,      l, a[0]);
        load_a_frags16(base, 32 * w + 16, l, a[1]);
    }
    __syncthreads();
    // half 1 (rows ib+128..ib+255): warps 4-7 extract
    load_tile(smT, g_featbH, ib + 128, tid);
    __syncthreads();
    if (w >= 4) {
        uint32_t base = smem_u32(smT);
        load_a_frags16(base, 32 * (w - 4),      l, a[0]);
        load_a_frags16(base, 32 * (w - 4) + 16, l, a[1]);
    }

    // exp2f(x * C2) == expf(x / T):  C2 = log2(e)/0.3
    const float C2 = 4.80898346963f;
    float sB[4] = {0.f, 0.f, 0.f, 0.f};

    uint32_t bbase = smem_u32(smT);
    uint32_t brow = (l & 7);
    uint32_t bkoff = 8 * (l >> 3);

    for (int jt = 0; jt < 64 / TSPLIT; jt++) {
        int jb = (split * (64 / TSPLIT) + jt) * 128;

        __syncthreads();   // previous tile (or A extraction) fully consumed
        load_tile(smT, g_featbH, jb, tid);
        __syncthreads();

        #pragma unroll
        for (int nb = 0; nb < 16; nb++) {
            float e0[4] = {0.f, 0.f, 0.f, 0.f}, o0[4] = {0.f, 0.f, 0.f, 0.f};
            float e1[4] = {0.f, 0.f, 0.f, 0.f}, o1[4] = {0.f, 0.f, 0.f, 0.f};
            #pragma unroll
            for (int kp = 0; kp < 4; kp++) {
                uint32_t b[4];
                LDSM4(b, bbase + (nb * 8 + brow) * STRIDE + (32 * kp + bkoff) * 2);
                HMMA4(e0, a[0][2 * kp],     b[0], b[1]);
                HMMA4(e1, a[1][2 * kp],     b[0], b[1]);
                HMMA4(o0, a[0][2 * kp + 1], b[2], b[3]);
                HMMA4(o1, a[1][2 * kp + 1], b[2], b[3]);
            }
            sB[0] += exp2f((e0[0] + o0[0]) * C2) + exp2f((e0[1] + o0[1]) * C2);
            sB[1] += exp2f((e0[2] + o0[2]) * C2) + exp2f((e0[3] + o0[3]) * C2);
            sB[2] += exp2f((e1[0] + o1[0]) * C2) + exp2f((e1[1] + o1[1]) * C2);
            sB[3] += exp2f((e1[2] + o1[2]) * C2) + exp2f((e1[3] + o1[3]) * C2);
        }
    }

    // deterministic reduce across the 4 lanes sharing each row
    #pragma unroll
    for (int q = 0; q < 4; q++) {
        #pragma unroll
        for (int d = 2; d; d >>= 1)
            sB[q] += __shfl_down_sync(0xffffffffu, sB[q], d, 4);
    }
    if ((l & 3) == 0) {
        int base_r = ib + 32 * w + (l >> 2);
        g_pb[split * BN + base_r]      = sB[0];
        g_pb[split * BN + base_r + 8]  = sB[1];
        g_pb[split * BN + base_r + 16] = sB[2];
        g_pb[split * BN + base_r + 24] = sB[3];
    }
}

// ---------------- combine: bottom (minus self) + closed-form positives -------
__global__ void combine_kernel() {
    int i = blockIdx.x * 256 + threadIdx.x;
    float bsum = 0.f;
    #pragma unroll
    for (int s = 0; s < TSPLIT; s++) bsum += g_pb[s * BN + i];

    int lab = g_lab[i];
    int cnt = g_cnt[lab] - 1;

    const float* fi = g_featn + (size_t)i * DN;
    const float* sc = g_S + (size_t)lab * DN;
    float dotS = 0.f, dotSelf = 0.f;
    #pragma unroll 8
    for (int k = 0; k < DN / 4; k++) {
        float4 f = ((const float4*)fi)[k];
        float4 s4 = ((const float4*)sc)[k];
        dotS += f.x * s4.x + f.y * s4.y + f.z * s4.z + f.w * s4.w;
        dotSelf += f.x * f.x + f.y * f.y + f.z * f.z + f.w * f.w;
    }
    const float invT = 1.0f / 0.3f;
    float bottom = bsum - __expf(dotSelf * invT);   // remove self-term
    float pp = (dotS - dotSelf) * invT;

    bool valid = (cnt > 0);
    g_peri[i]  = valid ? (pp / (float)cnt - logf(bottom)) : 0.f;
    g_valid[i] = valid ? 1.f : 0.f;
}

__global__ void final_kernel(float* __restrict__ out, long long scalar_idx) {
    int t = threadIdx.x;
    float sp = 0.f, sv = 0.f, sc = 0.f, smg = 0.f;
    for (int i = t; i < BN; i += 256) {
        sp += g_peri[i];
        sv += g_valid[i];
        sc += g_ce[i];
        smg += g_margin[i];
    }
    __shared__ float r0[256], r1[256], r2[256], r3[256];
    r0[t] = sp; r1[t] = sv; r2[t] = sc; r3[t] = smg;
    __syncthreads();
    for (int d = 128; d; d >>= 1) {
        if (t < d) { r0[t] += r0[t+d]; r1[t] += r1[t+d]; r2[t] += r2[t+d]; r3[t] += r3[t+d]; }
        __syncthreads();
    }
    if (t == 0) {
        float scl = -r0[0] / fmaxf(r1[0], 1.f);
        float ce  = r2[0] / (float)BN;
        float lm  = r3[0] / (2.f * (float)BN);
        out[scalar_idx] = 0.9f * ce + 0.1f * scl + 0.5f * lm;
    }
}

// ---------------- launch ------------------------------------------------------
extern "C" void kernel_launch(void* const* d_in, const int* in_sizes, int n_in,
                              void* d_out, int out_size) {
    const float* feat   = (const float*)d_in[0];
    const int*   labels = (const int*)d_in[1];
    const float* means  = (const float*)d_in[2];
    float* out = (float*)d_out;

    static cudaStream_t sB = nullptr;
    static cudaEvent_t  eF = nullptr, eJ = nullptr;
    static int initTried = 0;
    if (!initTried) {
        initTried = 1;
        if (cudaStreamCreateWithFlags(&sB, cudaStreamNonBlocking) != cudaSuccess) sB = nullptr;
        if (sB) {
            if (cudaEventCreateWithFlags(&eF, cudaEventDisableTiming) != cudaSuccess) { eF = nullptr; }
            if (cudaEventCreateWithFlags(&eJ, cudaEventDisableTiming) != cudaSuccess) { eJ = nullptr; }
            if (!eF || !eJ) sB = nullptr;
        }
        cudaFuncSetAttribute(nsd_mma_kernel, cudaFuncAttributeMaxDynamicSharedMemorySize, SMEM_NSD);
        cudaFuncSetAttribute(scl_mma_kernel, cudaFuncAttributeMaxDynamicSharedMemorySize, SMEM_SCL);
    }
    bool fork = (sB != nullptr);

    prep_feat_kernel<<<BN / 8, dim3(32, 8)>>>(feat, labels);

    if (fork) {
        cudaEventRecord(eF, 0);
        cudaStreamWaitEvent(sB, eF, 0);
        scl_mma_kernel<<<dim3(BN / 256, TSPLIT), 256, SMEM_SCL, sB>>>();
        cudaEventRecord(eJ, sB);
    }

    prep_means_kernel<<<CPAD / 8, dim3(32, 8)>>>(means);
    nsd_mma_kernel<<<dim3(BN / 128, CPAD / 128), 256, SMEM_NSD>>>(out);
    ce_kernel<<<BN / 8, 256>>>(out);
    class_sum_kernel<<<CN / 8, 256>>>();

    if (fork) {
        cudaStreamWaitEvent(0, eJ, 0);
    } else {
        scl_mma_kernel<<<dim3(BN / 256, TSPLIT), 256, SMEM_SCL>>>();
    }

    combine_kernel<<<BN / 256, 256>>>();
    final_kernel<<<1, 256>>>(out, (long long)out_size - 1);
}

// round 16
// speedup vs baseline: 1.4927x; 1.4927x over previous
#include <cuda_runtime.h>
#include <cuda_bf16.h>
#include <math.h>
#include <cstdint>

#define BN 8192
#define CN 1000
#define CPAD 1024
#define DN 128
#define TSPLIT 8
#define STRIDE 272                 // bytes per tile row: 256 data + 16 pad (conflict-free ldmatrix)
#define TILE_BYTES (128 * STRIDE)  // 34816
#define SMEM_NSD (2 * TILE_BYTES + 512)
#define SMEM_SCL (TILE_BYTES + 512)

// ---------------- scratch ---------------------------------------------------
__device__ float g_featn[BN * DN];
__device__ __nv_bfloat16 g_featbH[BN * DN];
__device__ __nv_bfloat16 g_featbL[BN * DN];
__device__ float g_meansn[CN * DN];
__device__ __nv_bfloat16 g_meansBH[CPAD * DN];
__device__ __nv_bfloat16 g_meansBL[CPAD * DN];
__device__ float g_XX[BN];
__device__ float g_YY[CN];
__device__ int   g_lab[BN];
__device__ float g_pb[TSPLIT * BN];    // bottom partials (self included; removed in combine)
__device__ float g_S[CN * DN];         // class feature sums
__device__ int   g_cnt[CN];            // class counts
__device__ float g_ce[BN];
__device__ float g_margin[BN];
__device__ float g_peri[BN];
__device__ float g_valid[BN];

__device__ __forceinline__ uint32_t smem_u32(const void* p) {
    uint32_t a;
    asm("{ .reg .u64 t; cvta.to.shared.u64 t, %1; cvt.u32.u64 %0, t; }" : "=r"(a) : "l"(p));
    return a;
}
__device__ __forceinline__ void bf16_split(float x, __nv_bfloat16& hi, __nv_bfloat16& lo) {
    hi = __float2bfloat16(x);
    lo = __float2bfloat16(x - __bfloat162float(hi));
}

#define HMMA4(ACC, A, B0, B1) \
    asm("mma.sync.aligned.m16n8k16.row.col.f32.bf16.bf16.f32 " \
        "{%0,%1,%2,%3}, {%4,%5,%6,%7}, {%8,%9}, {%0,%1,%2,%3};" \
        : "+f"((ACC)[0]), "+f"((ACC)[1]), "+f"((ACC)[2]), "+f"((ACC)[3]) \
        : "r"((A)[0]), "r"((A)[1]), "r"((A)[2]), "r"((A)[3]), "r"(B0), "r"(B1))

#define LDSM4(R, ADDR) \
    asm volatile("ldmatrix.sync.aligned.m8n8.x4.shared.b16 {%0,%1,%2,%3}, [%4];" \
                 : "=r"((R)[0]), "=r"((R)[1]), "=r"((R)[2]), "=r"((R)[3]) : "r"(ADDR))

// ---------------- prep -------------------------------------------------------
__global__ void prep_feat_kernel(const float* __restrict__ feat,
                                 const int* __restrict__ labels) {
    int row = blockIdx.x * 8 + threadIdx.y;
    int lane = threadIdx.x;
    float4 v = ((const float4*)(feat + (size_t)row * DN))[lane];
    float ss = v.x * v.x + v.y * v.y + v.z * v.z + v.w * v.w;
    #pragma unroll
    for (int d = 16; d; d >>= 1) ss += __shfl_xor_sync(0xffffffffu, ss, d);
    float inv = 1.0f / fmaxf(sqrtf(ss), 1e-12f);
    float4 o = make_float4(v.x * inv, v.y * inv, v.z * inv, v.w * inv);
    ((float4*)(g_featn + (size_t)row * DN))[lane] = o;

    __nv_bfloat16 hx, lx, hy, ly, hz, lz, hw, lw;
    bf16_split(o.x, hx, lx); bf16_split(o.y, hy, ly);
    bf16_split(o.z, hz, lz); bf16_split(o.w, hw, lw);
    __nv_bfloat162 h0 = __nv_bfloat162(hx, hy), h1 = __nv_bfloat162(hz, hw);
    __nv_bfloat162 l0 = __nv_bfloat162(lx, ly), l1 = __nv_bfloat162(lz, lw);
    ((uint2*)(g_featbH + (size_t)row * DN))[lane] = make_uint2(*(uint32_t*)&h0, *(uint32_t*)&h1);
    ((uint2*)(g_featbL + (size_t)row * DN))[lane] = make_uint2(*(uint32_t*)&l0, *(uint32_t*)&l1);
    if (lane == 0) {
        g_XX[row] = ss * inv * inv;
        g_lab[row] = labels[row];
    }
}

__global__ void prep_means_kernel(const float* __restrict__ means) {
    int row = blockIdx.x * 8 + threadIdx.y;   // 128 blocks * 8 = 1024 (padded)
    int lane = threadIdx.x;
    float4 v = make_float4(0.f, 0.f, 0.f, 0.f);
    if (row < CN) v = ((const float4*)(means + (size_t)row * DN))[lane];
    float ss = v.x * v.x + v.y * v.y + v.z * v.z + v.w * v.w;
    #pragma unroll
    for (int d = 16; d; d >>= 1) ss += __shfl_xor_sync(0xffffffffu, ss, d);
    float inv = 1.0f / fmaxf(sqrtf(ss), 1e-12f);

    __nv_bfloat16 hx, lx, hy, ly, hz, lz, hw, lw;
    bf16_split(v.x, hx, lx); bf16_split(v.y, hy, ly);
    bf16_split(v.z, hz, lz); bf16_split(v.w, hw, lw);
    __nv_bfloat162 h0 = __nv_bfloat162(hx, hy), h1 = __nv_bfloat162(hz, hw);
    __nv_bfloat162 l0 = __nv_bfloat162(lx, ly), l1 = __nv_bfloat162(lz, lw);
    ((uint2*)(g_meansBH + (size_t)row * DN))[lane] = make_uint2(*(uint32_t*)&h0, *(uint32_t*)&h1);
    ((uint2*)(g_meansBL + (size_t)row * DN))[lane] = make_uint2(*(uint32_t*)&l0, *(uint32_t*)&l1);

    if (row < CN) {
        float4 o = make_float4(v.x * inv, v.y * inv, v.z * inv, v.w * inv);
        ((float4*)(g_meansn + (size_t)row * DN))[lane] = o;
        if (lane == 0) g_YY[row] = ss;
    }
}

// ---------------- class sums: one warp per class (deterministic) -------------
__global__ void __launch_bounds__(256) class_sum_kernel() {
    int w = threadIdx.x >> 5, l = threadIdx.x & 31;
    int c = blockIdx.x * 8 + w;
    float4 acc = make_float4(0.f, 0.f, 0.f, 0.f);
    int count = 0;
    for (int base = 0; base < BN; base += 32) {
        int lb = g_lab[base + l];
        unsigned m = __ballot_sync(0xffffffffu, lb == c);
        count += __popc(m);
        while (m) {
            int j = __ffs(m) - 1;
            m &= m - 1;
            float4 f = ((const float4*)(g_featn + (size_t)(base + j) * DN))[l];
            acc.x += f.x; acc.y += f.y; acc.z += f.z; acc.w += f.w;
        }
    }
    ((float4*)(g_S + (size_t)c * DN))[l] = acc;
    if (l == 0) g_cnt[c] = count;
}

// copy a 128-row bf16 tile into padded smem; each thread: one half-row (128 B)
__device__ __forceinline__ void load_tile(char* dst, const __nv_bfloat16* src_base,
                                          int row0, int tid) {
    int r = tid >> 1, h = tid & 1;
    const uint4* src = (const uint4*)(src_base + (size_t)(row0 + r) * DN + h * 64);
    uint4* d = (uint4*)(dst + r * STRIDE + h * 128);
    #pragma unroll
    for (int i = 0; i < 8; i++) d[i] = src[i];
}

// extract a warp's 16-row A fragments (8 k-steps) starting at tile row `row0`
__device__ __forceinline__ void load_a_frags16(uint32_t base, int row0, int l, uint32_t a[8][4]) {
    uint32_t row = row0 + (l & 15);
    uint32_t koff = 8 * (l >> 4);
    #pragma unroll
    for (int ks = 0; ks < 8; ks++) {
        uint32_t addr = base + row * STRIDE + (16 * ks + koff) * 2;
        LDSM4(a[ks], addr);
    }
}

// ---------------- nsd GEMM via split-bf16 mma.sync ---------------------------
__global__ void __launch_bounds__(256) nsd_mma_kernel(float* __restrict__ out) {
    extern __shared__ __align__(16) char sm[];
    char* smX = sm;
    char* smY = sm + TILE_BYTES;
    float* smYY = (float*)(sm + 2 * TILE_BYTES);

    int tid = threadIdx.x;
    int w = tid >> 5, l = tid & 31;
    int ib = blockIdx.x * 128;
    int cb = blockIdx.y * 128;

    load_tile(smX, g_featbH, ib, tid);
    load_tile(smY, g_featbL, ib, tid);
    __syncthreads();

    uint32_t ah[8][4], al[8][4];
    load_a_frags16(smem_u32(smX), 16 * w, l, ah);
    load_a_frags16(smem_u32(smY), 16 * w, l, al);
    __syncthreads();

    load_tile(smX, g_meansBH, cb, tid);
    load_tile(smY, g_meansBL, cb, tid);
    if (tid < 128) {
        int c = cb + tid;
        smYY[tid] = (c < CN) ? (-0.5f * g_YY[c]) : 0.f;
    }
    __syncthreads();

    int r0 = 16 * w + (l >> 2), r1 = r0 + 8;
    int i0 = ib + r0, i1 = ib + r1;
    float nx0 = -0.5f * g_XX[i0], nx1 = -0.5f * g_XX[i1];

    uint32_t baseH = smem_u32(smX), baseL = smem_u32(smY);
    uint32_t brow = (l & 7);
    uint32_t bkoff = 8 * (l >> 3);

    #pragma unroll
    for (int nb = 0; nb < 16; nb++) {
        float hh[4] = {0.f, 0.f, 0.f, 0.f};
        float lh[4] = {0.f, 0.f, 0.f, 0.f};
        float hl[4] = {0.f, 0.f, 0.f, 0.f};
        #pragma unroll
        for (int kp = 0; kp < 4; kp++) {
            uint32_t off = (nb * 8 + brow) * STRIDE + (32 * kp + bkoff) * 2;
            uint32_t bh[4], bl[4];
            LDSM4(bh, baseH + off);
            LDSM4(bl, baseL + off);
            HMMA4(hh, ah[2 * kp],     bh[0], bh[1]);
            HMMA4(lh, al[2 * kp],     bh[0], bh[1]);
            HMMA4(hl, ah[2 * kp],     bl[0], bl[1]);
            HMMA4(hh, ah[2 * kp + 1], bh[2], bh[3]);
            HMMA4(lh, al[2 * kp + 1], bh[2], bh[3]);
            HMMA4(hl, ah[2 * kp + 1], bl[2], bl[3]);
        }
        int colloc = nb * 8 + 2 * (l & 3);
        int col = cb + colloc;
        float y0 = smYY[colloc], y1 = smYY[colloc + 1];
        if (col < CN) {
            out[(size_t)i0 * CN + col] = nx0 + (hh[0] + lh[0] + hl[0]) + y0;
            out[(size_t)i1 * CN + col] = nx1 + (hh[2] + lh[2] + hl[2]) + y0;
        }
        if (col + 1 < CN) {
            out[(size_t)i0 * CN + col + 1] = nx0 + (hh[1] + lh[1] + hl[1]) + y1;
            out[(size_t)i1 * CN + col + 1] = nx1 + (hh[3] + lh[3] + hl[3]) + y1;
        }
    }
}

// ---------------- CE + margin: one warp per row ------------------------------
__global__ void __launch_bounds__(256) ce_kernel(const float* __restrict__ nsd) {
    int w = threadIdx.x >> 5, l = threadIdx.x & 31;
    int i = blockIdx.x * 8 + w;
    int lab = g_lab[i];
    const float4* row = (const float4*)(nsd + (size_t)i * CN);

    float4 v[8];
    float m = -1e30f, vlab = -1e30f;
    #pragma unroll
    for (int k = 0; k < 8; k++) {
        int idx = l + 32 * k;
        float4 x = make_float4(-1e30f, -1e30f, -1e30f, -1e30f);
        if (idx < 250) {
            x = row[idx];
            int c0 = idx * 4;
            if (lab == c0)     { x.x *= 1.5f; vlab = x.x; }
            if (lab == c0 + 1) { x.y *= 1.5f; vlab = x.y; }
            if (lab == c0 + 2) { x.z *= 1.5f; vlab = x.z; }
            if (lab == c0 + 3) { x.w *= 1.5f; vlab = x.w; }
            m = fmaxf(m, fmaxf(fmaxf(x.x, x.y), fmaxf(x.z, x.w)));
        }
        v[k] = x;
    }
    #pragma unroll
    for (int d = 16; d; d >>= 1) {
        m = fmaxf(m, __shfl_xor_sync(0xffffffffu, m, d));
        vlab = fmaxf(vlab, __shfl_xor_sync(0xffffffffu, vlab, d));
    }
    float e = 0.f;
    #pragma unroll
    for (int k = 0; k < 8; k++)
        e += __expf(v[k].x - m) + __expf(v[k].y - m)
           + __expf(v[k].z - m) + __expf(v[k].w - m);
    #pragma unroll
    for (int d = 16; d; d >>= 1) e += __shfl_xor_sync(0xffffffffu, e, d);
    if (l == 0) g_ce[i] = -(vlab - m - logf(e));

    float4 f  = ((const float4*)(g_featn  + (size_t)i   * DN))[l];
    float4 mm = ((const float4*)(g_meansn + (size_t)lab * DN))[l];
    float dx = f.x - mm.x, dy = f.y - mm.y, dz = f.z - mm.z, dw = f.w - mm.w;
    float ms = dx * dx + dy * dy + dz * dz + dw * dw;
    #pragma unroll
    for (int d = 16; d; d >>= 1) ms += __shfl_xor_sync(0xffffffffu, ms, d);
    if (l == 0) g_margin[i] = ms;
}

// ---------------- SCL: bottom-only, mask-free fused GEMM + row reduction -----
// CTA = 256 i-rows x 128 j-cols; 8 warps x 32 rows -> 4 HMMA per B LDSM.x4.
// Self-term included here; combine subtracts exp(f_i.f_i/T).
__global__ void __launch_bounds__(256, 2) scl_mma_kernel() {
    extern __shared__ __align__(16) char sm[];
    char* smT = sm;

    int tid = threadIdx.x;
    int w = tid >> 5;
    int l = tid & 31;
    int ib = blockIdx.x * 256;
    int split = blockIdx.y;

    uint32_t a[2][8][4];   // [strip 0/1][k-step][frag]

    // half 0 (rows ib..ib+127): warps 0-3 extract their 2 strips
    load_tile(smT, g_featbH, ib, tid);
    __syncthreads();
    if (w < 4) {
        uint32_t base = smem_u32(smT);
        load_a_frags16(base, 32 * w,      l, a[0]);
        load_a_frags16(base, 32 * w + 16, l, a[1]);
    }
    __syncthreads();
    // half 1 (rows ib+128..ib+255): warps 4-7 extract
    load_tile(smT, g_featbH, ib + 128, tid);
    __syncthreads();
    if (w >= 4) {
        uint32_t base = smem_u32(smT);
        load_a_frags16(base, 32 * (w - 4),      l, a[0]);
        load_a_frags16(base, 32 * (w - 4) + 16, l, a[1]);
    }

    // exp2f(x * C2) == expf(x / T):  C2 = log2(e)/0.3
    const float C2 = 4.80898346963f;
    float sB[4] = {0.f, 0.f, 0.f, 0.f};

    uint32_t bbase = smem_u32(smT);
    uint32_t brow = (l & 7);
    uint32_t bkoff = 8 * (l >> 3);

    for (int jt = 0; jt < 64 / TSPLIT; jt++) {
        int jb = (split * (64 / TSPLIT) + jt) * 128;

        __syncthreads();   // previous tile (or A extraction) fully consumed
        load_tile(smT, g_featbH, jb, tid);
        __syncthreads();

        #pragma unroll
        for (int nb = 0; nb < 16; nb++) {
            float e0[4] = {0.f, 0.f, 0.f, 0.f}, o0[4] = {0.f, 0.f, 0.f, 0.f};
            float e1[4] = {0.f, 0.f, 0.f, 0.f}, o1[4] = {0.f, 0.f, 0.f, 0.f};
            #pragma unroll
            for (int kp = 0; kp < 4; kp++) {
                uint32_t b[4];
                LDSM4(b, bbase + (nb * 8 + brow) * STRIDE + (32 * kp + bkoff) * 2);
                HMMA4(e0, a[0][2 * kp],     b[0], b[1]);
                HMMA4(e1, a[1][2 * kp],     b[0], b[1]);
                HMMA4(o0, a[0][2 * kp + 1], b[2], b[3]);
                HMMA4(o1, a[1][2 * kp + 1], b[2], b[3]);
            }
            sB[0] += exp2f((e0[0] + o0[0]) * C2) + exp2f((e0[1] + o0[1]) * C2);
            sB[1] += exp2f((e0[2] + o0[2]) * C2) + exp2f((e0[3] + o0[3]) * C2);
            sB[2] += exp2f((e1[0] + o1[0]) * C2) + exp2f((e1[1] + o1[1]) * C2);
            sB[3] += exp2f((e1[2] + o1[2]) * C2) + exp2f((e1[3] + o1[3]) * C2);
        }
    }

    // deterministic reduce across the 4 lanes sharing each row
    #pragma unroll
    for (int q = 0; q < 4; q++) {
        #pragma unroll
        for (int d = 2; d; d >>= 1)
            sB[q] += __shfl_down_sync(0xffffffffu, sB[q], d, 4);
    }
    if ((l & 3) == 0) {
        int base_r = ib + 32 * w + (l >> 2);
        g_pb[split * BN + base_r]      = sB[0];
        g_pb[split * BN + base_r + 8]  = sB[1];
        g_pb[split * BN + base_r + 16] = sB[2];
        g_pb[split * BN + base_r + 24] = sB[3];
    }
}

// ---------------- combine: bottom (minus self) + closed-form positives -------
__global__ void combine_kernel() {
    int i = blockIdx.x * 256 + threadIdx.x;
    float bsum = 0.f;
    #pragma unroll
    for (int s = 0; s < TSPLIT; s++) bsum += g_pb[s * BN + i];

    int lab = g_lab[i];
    int cnt = g_cnt[lab] - 1;

    const float* fi = g_featn + (size_t)i * DN;
    const float* sc = g_S + (size_t)lab * DN;
    float dotS = 0.f, dotSelf = 0.f;
    #pragma unroll 8
    for (int k = 0; k < DN / 4; k++) {
        float4 f = ((const float4*)fi)[k];
        float4 s4 = ((const float4*)sc)[k];
        dotS += f.x * s4.x + f.y * s4.y + f.z * s4.z + f.w * s4.w;
        dotSelf += f.x * f.x + f.y * f.y + f.z * f.z + f.w * f.w;
    }
    const float invT = 1.0f / 0.3f;
    float bottom = bsum - __expf(dotSelf * invT);   // remove self-term
    float pp = (dotS - dotSelf) * invT;

    bool valid = (cnt > 0);
    g_peri[i]  = valid ? (pp / (float)cnt - logf(bottom)) : 0.f;
    g_valid[i] = valid ? 1.f : 0.f;
}

__global__ void final_kernel(float* __restrict__ out, long long scalar_idx) {
    int t = threadIdx.x;
    float sp = 0.f, sv = 0.f, sc = 0.f, smg = 0.f;
    for (int i = t; i < BN; i += 256) {
        sp += g_peri[i];
        sv += g_valid[i];
        sc += g_ce[i];
        smg += g_margin[i];
    }
    __shared__ float r0[256], r1[256], r2[256], r3[256];
    r0[t] = sp; r1[t] = sv; r2[t] = sc; r3[t] = smg;
    __syncthreads();
    for (int d = 128; d; d >>= 1) {
        if (t < d) { r0[t] += r0[t+d]; r1[t] += r1[t+d]; r2[t] += r2[t+d]; r3[t] += r3[t+d]; }
        __syncthreads();
    }
    if (t == 0) {
        float scl = -r0[0] / fmaxf(r1[0], 1.f);
        float ce  = r2[0] / (float)BN;
        float lm  = r3[0] / (2.f * (float)BN);
        out[scalar_idx] = 0.9f * ce + 0.1f * scl + 0.5f * lm;
    }
}

// ---------------- launch ------------------------------------------------------
extern "C" void kernel_launch(void* const* d_in, const int* in_sizes, int n_in,
                              void* d_out, int out_size) {
    const float* feat   = (const float*)d_in[0];
    const int*   labels = (const int*)d_in[1];
    const float* means  = (const float*)d_in[2];
    float* out = (float*)d_out;

    static cudaStream_t sB = nullptr;
    static cudaEvent_t  eF = nullptr, eJ = nullptr;
    static int initTried = 0;
    if (!initTried) {
        initTried = 1;
        if (cudaStreamCreateWithFlags(&sB, cudaStreamNonBlocking) != cudaSuccess) sB = nullptr;
        if (sB) {
            if (cudaEventCreateWithFlags(&eF, cudaEventDisableTiming) != cudaSuccess) { eF = nullptr; }
            if (cudaEventCreateWithFlags(&eJ, cudaEventDisableTiming) != cudaSuccess) { eJ = nullptr; }
            if (!eF || !eJ) sB = nullptr;
        }
        cudaFuncSetAttribute(nsd_mma_kernel, cudaFuncAttributeMaxDynamicSharedMemorySize, SMEM_NSD);
        cudaFuncSetAttribute(scl_mma_kernel, cudaFuncAttributeMaxDynamicSharedMemorySize, SMEM_SCL);
    }
    bool fork = (sB != nullptr);

    prep_feat_kernel<<<BN / 8, dim3(32, 8)>>>(feat, labels);

    if (fork) {
        cudaEventRecord(eF, 0);
        cudaStreamWaitEvent(sB, eF, 0);
        scl_mma_kernel<<<dim3(BN / 256, TSPLIT), 256, SMEM_SCL, sB>>>();
        cudaEventRecord(eJ, sB);
    }

    prep_means_kernel<<<CPAD / 8, dim3(32, 8)>>>(means);
    nsd_mma_kernel<<<dim3(BN / 128, CPAD / 128), 256, SMEM_NSD>>>(out);
    ce_kernel<<<BN / 8, 256>>>(out);
    class_sum_kernel<<<CN / 8, 256>>>();

    if (fork) {
        cudaStreamWaitEvent(0, eJ, 0);
    } else {
        scl_mma_kernel<<<dim3(BN / 256, TSPLIT), 256, SMEM_SCL>>>();
    }

    combine_kernel<<<BN / 256, 256>>>();
    final_kernel<<<1, 256>>>(out, (long long)out_size - 1);
}

// round 17
// speedup vs baseline: 1.4951x; 1.0017x over previous
#include <cuda_runtime.h>
#include <cuda_bf16.h>
#include <math.h>
#include <cstdint>

#define BN 8192
#define CN 1000
#define CPAD 1024
#define DN 128
#define TSPLIT 8
#define STRIDE 272                 // bytes per tile row: 256 data + 16 pad (conflict-free ldmatrix)
#define TILE_BYTES (128 * STRIDE)  // 34816
#define SMEM_NSD (2 * TILE_BYTES + 512)
#define SMEM_SCL (TILE_BYTES + 512)

// ---------------- scratch ---------------------------------------------------
__device__ float g_featn[BN * DN];
__device__ __nv_bfloat16 g_featbH[BN * DN];
__device__ __nv_bfloat16 g_featbL[BN * DN];
__device__ float g_meansn[CN * DN];
__device__ __nv_bfloat16 g_meansBH[CPAD * DN];
__device__ __nv_bfloat16 g_meansBL[CPAD * DN];
__device__ float g_XX[BN];
__device__ float g_YY[CN];
__device__ int   g_lab[BN];
__device__ float g_pb[TSPLIT * BN];    // bottom partials (self included; removed in combine)
__device__ float g_S[CN * DN];         // class feature sums
__device__ int   g_cnt[CN];            // class counts
__device__ float g_ce[BN];
__device__ float g_margin[BN];
__device__ float g_peri[BN];
__device__ float g_valid[BN];

__device__ __forceinline__ uint32_t smem_u32(const void* p) {
    uint32_t a;
    asm("{ .reg .u64 t; cvta.to.shared.u64 t, %1; cvt.u32.u64 %0, t; }" : "=r"(a) : "l"(p));
    return a;
}
__device__ __forceinline__ void bf16_split(float x, __nv_bfloat16& hi, __nv_bfloat16& lo) {
    hi = __float2bfloat16(x);
    lo = __float2bfloat16(x - __bfloat162float(hi));
}
// raw MUFU.EX2 — same unit/accuracy as __expf, no libm wrapper
__device__ __forceinline__ float ex2(float x) {
    float r;
    asm("ex2.approx.ftz.f32 %0, %1;" : "=f"(r) : "f"(x));
    return r;
}

#define HMMA4(ACC, A, B0, B1) \
    asm("mma.sync.aligned.m16n8k16.row.col.f32.bf16.bf16.f32 " \
        "{%0,%1,%2,%3}, {%4,%5,%6,%7}, {%8,%9}, {%0,%1,%2,%3};" \
        : "+f"((ACC)[0]), "+f"((ACC)[1]), "+f"((ACC)[2]), "+f"((ACC)[3]) \
        : "r"((A)[0]), "r"((A)[1]), "r"((A)[2]), "r"((A)[3]), "r"(B0), "r"(B1))

#define LDSM4(R, ADDR) \
    asm volatile("ldmatrix.sync.aligned.m8n8.x4.shared.b16 {%0,%1,%2,%3}, [%4];" \
                 : "=r"((R)[0]), "=r"((R)[1]), "=r"((R)[2]), "=r"((R)[3]) : "r"(ADDR))

// ---------------- prep -------------------------------------------------------
__global__ void prep_feat_kernel(const float* __restrict__ feat,
                                 const int* __restrict__ labels) {
    int row = blockIdx.x * 8 + threadIdx.y;
    int lane = threadIdx.x;
    float4 v = ((const float4*)(feat + (size_t)row * DN))[lane];
    float ss = v.x * v.x + v.y * v.y + v.z * v.z + v.w * v.w;
    #pragma unroll
    for (int d = 16; d; d >>= 1) ss += __shfl_xor_sync(0xffffffffu, ss, d);
    float inv = 1.0f / fmaxf(sqrtf(ss), 1e-12f);
    float4 o = make_float4(v.x * inv, v.y * inv, v.z * inv, v.w * inv);
    ((float4*)(g_featn + (size_t)row * DN))[lane] = o;

    __nv_bfloat16 hx, lx, hy, ly, hz, lz, hw, lw;
    bf16_split(o.x, hx, lx); bf16_split(o.y, hy, ly);
    bf16_split(o.z, hz, lz); bf16_split(o.w, hw, lw);
    __nv_bfloat162 h0 = __nv_bfloat162(hx, hy), h1 = __nv_bfloat162(hz, hw);
    __nv_bfloat162 l0 = __nv_bfloat162(lx, ly), l1 = __nv_bfloat162(lz, lw);
    ((uint2*)(g_featbH + (size_t)row * DN))[lane] = make_uint2(*(uint32_t*)&h0, *(uint32_t*)&h1);
    ((uint2*)(g_featbL + (size_t)row * DN))[lane] = make_uint2(*(uint32_t*)&l0, *(uint32_t*)&l1);
    if (lane == 0) {
        g_XX[row] = ss * inv * inv;
        g_lab[row] = labels[row];
    }
}

__global__ void prep_means_kernel(const float* __restrict__ means) {
    int row = blockIdx.x * 8 + threadIdx.y;   // 128 blocks * 8 = 1024 (padded)
    int lane = threadIdx.x;
    float4 v = make_float4(0.f, 0.f, 0.f, 0.f);
    if (row < CN) v = ((const float4*)(means + (size_t)row * DN))[lane];
    float ss = v.x * v.x + v.y * v.y + v.z * v.z + v.w * v.w;
    #pragma unroll
    for (int d = 16; d; d >>= 1) ss += __shfl_xor_sync(0xffffffffu, ss, d);
    float inv = 1.0f / fmaxf(sqrtf(ss), 1e-12f);

    __nv_bfloat16 hx, lx, hy, ly, hz, lz, hw, lw;
    bf16_split(v.x, hx, lx); bf16_split(v.y, hy, ly);
    bf16_split(v.z, hz, lz); bf16_split(v.w, hw, lw);
    __nv_bfloat162 h0 = __nv_bfloat162(hx, hy), h1 = __nv_bfloat162(hz, hw);
    __nv_bfloat162 l0 = __nv_bfloat162(lx, ly), l1 = __nv_bfloat162(lz, lw);
    ((uint2*)(g_meansBH + (size_t)row * DN))[lane] = make_uint2(*(uint32_t*)&h0, *(uint32_t*)&h1);
    ((uint2*)(g_meansBL + (size_t)row * DN))[lane] = make_uint2(*(uint32_t*)&l0, *(uint32_t*)&l1);

    if (row < CN) {
        float4 o = make_float4(v.x * inv, v.y * inv, v.z * inv, v.w * inv);
        ((float4*)(g_meansn + (size_t)row * DN))[lane] = o;
        if (lane == 0) g_YY[row] = ss;
    }
}

// ---------------- class sums: one warp per class (deterministic) -------------
__global__ void __launch_bounds__(256) class_sum_kernel() {
    int w = threadIdx.x >> 5, l = threadIdx.x & 31;
    int c = blockIdx.x * 8 + w;
    float4 acc = make_float4(0.f, 0.f, 0.f, 0.f);
    int count = 0;
    for (int base = 0; base < BN; base += 32) {
        int lb = g_lab[base + l];
        unsigned m = __ballot_sync(0xffffffffu, lb == c);
        count += __popc(m);
        while (m) {
            int j = __ffs(m) - 1;
            m &= m - 1;
            float4 f = ((const float4*)(g_featn + (size_t)(base + j) * DN))[l];
            acc.x += f.x; acc.y += f.y; acc.z += f.z; acc.w += f.w;
        }
    }
    ((float4*)(g_S + (size_t)c * DN))[l] = acc;
    if (l == 0) g_cnt[c] = count;
}

// copy a 128-row bf16 tile into padded smem; each thread: one half-row (128 B)
__device__ __forceinline__ void load_tile(char* dst, const __nv_bfloat16* src_base,
                                          int row0, int tid) {
    int r = tid >> 1, h = tid & 1;
    const uint4* src = (const uint4*)(src_base + (size_t)(row0 + r) * DN + h * 64);
    uint4* d = (uint4*)(dst + r * STRIDE + h * 128);
    #pragma unroll
    for (int i = 0; i < 8; i++) d[i] = src[i];
}

// extract a warp's 16-row A fragments (8 k-steps) starting at tile row `row0`
__device__ __forceinline__ void load_a_frags16(uint32_t base, int row0, int l, uint32_t a[8][4]) {
    uint32_t row = row0 + (l & 15);
    uint32_t koff = 8 * (l >> 4);
    #pragma unroll
    for (int ks = 0; ks < 8; ks++) {
        uint32_t addr = base + row * STRIDE + (16 * ks + koff) * 2;
        LDSM4(a[ks], addr);
    }
}

// ---------------- nsd GEMM via split-bf16 mma.sync ---------------------------
__global__ void __launch_bounds__(256) nsd_mma_kernel(float* __restrict__ out) {
    extern __shared__ __align__(16) char sm[];
    char* smX = sm;
    char* smY = sm + TILE_BYTES;
    float* smYY = (float*)(sm + 2 * TILE_BYTES);

    int tid = threadIdx.x;
    int w = tid >> 5, l = tid & 31;
    int ib = blockIdx.x * 128;
    int cb = blockIdx.y * 128;

    load_tile(smX, g_featbH, ib, tid);
    load_tile(smY, g_featbL, ib, tid);
    __syncthreads();

    uint32_t ah[8][4], al[8][4];
    load_a_frags16(smem_u32(smX), 16 * w, l, ah);
    load_a_frags16(smem_u32(smY), 16 * w, l, al);
    __syncthreads();

    load_tile(smX, g_meansBH, cb, tid);
    load_tile(smY, g_meansBL, cb, tid);
    if (tid < 128) {
        int c = cb + tid;
        smYY[tid] = (c < CN) ? (-0.5f * g_YY[c]) : 0.f;
    }
    __syncthreads();

    int r0 = 16 * w + (l >> 2), r1 = r0 + 8;
    int i0 = ib + r0, i1 = ib + r1;
    float nx0 = -0.5f * g_XX[i0], nx1 = -0.5f * g_XX[i1];

    uint32_t baseH = smem_u32(smX), baseL = smem_u32(smY);
    uint32_t brow = (l & 7);
    uint32_t bkoff = 8 * (l >> 3);

    #pragma unroll
    for (int nb = 0; nb < 16; nb++) {
        float hh[4] = {0.f, 0.f, 0.f, 0.f};
        float lh[4] = {0.f, 0.f, 0.f, 0.f};
        float hl[4] = {0.f, 0.f, 0.f, 0.f};
        #pragma unroll
        for (int kp = 0; kp < 4; kp++) {
            uint32_t off = (nb * 8 + brow) * STRIDE + (32 * kp + bkoff) * 2;
            uint32_t bh[4], bl[4];
            LDSM4(bh, baseH + off);
            LDSM4(bl, baseL + off);
            HMMA4(hh, ah[2 * kp],     bh[0], bh[1]);
            HMMA4(lh, al[2 * kp],     bh[0], bh[1]);
            HMMA4(hl, ah[2 * kp],     bl[0], bl[1]);
            HMMA4(hh, ah[2 * kp + 1], bh[2], bh[3]);
            HMMA4(lh, al[2 * kp + 1], bh[2], bh[3]);
            HMMA4(hl, ah[2 * kp + 1], bl[2], bl[3]);
        }
        int colloc = nb * 8 + 2 * (l & 3);
        int col = cb + colloc;
        float y0 = smYY[colloc], y1 = smYY[colloc + 1];
        if (col < CN) {
            out[(size_t)i0 * CN + col] = nx0 + (hh[0] + lh[0] + hl[0]) + y0;
            out[(size_t)i1 * CN + col] = nx1 + (hh[2] + lh[2] + hl[2]) + y0;
        }
        if (col + 1 < CN) {
            out[(size_t)i0 * CN + col + 1] = nx0 + (hh[1] + lh[1] + hl[1]) + y1;
            out[(size_t)i1 * CN + col + 1] = nx1 + (hh[3] + lh[3] + hl[3]) + y1;
        }
    }
}

// ---------------- CE + margin: one warp per row ------------------------------
__global__ void __launch_bounds__(256) ce_kernel(const float* __restrict__ nsd) {
    int w = threadIdx.x >> 5, l = threadIdx.x & 31;
    int i = blockIdx.x * 8 + w;
    int lab = g_lab[i];
    const float4* row = (const float4*)(nsd + (size_t)i * CN);

    float4 v[8];
    float m = -1e30f, vlab = -1e30f;
    #pragma unroll
    for (int k = 0; k < 8; k++) {
        int idx = l + 32 * k;
        float4 x = make_float4(-1e30f, -1e30f, -1e30f, -1e30f);
        if (idx < 250) {
            x = row[idx];
            int c0 = idx * 4;
            if (lab == c0)     { x.x *= 1.5f; vlab = x.x; }
            if (lab == c0 + 1) { x.y *= 1.5f; vlab = x.y; }
            if (lab == c0 + 2) { x.z *= 1.5f; vlab = x.z; }
            if (lab == c0 + 3) { x.w *= 1.5f; vlab = x.w; }
            m = fmaxf(m, fmaxf(fmaxf(x.x, x.y), fmaxf(x.z, x.w)));
        }
        v[k] = x;
    }
    #pragma unroll
    for (int d = 16; d; d >>= 1) {
        m = fmaxf(m, __shfl_xor_sync(0xffffffffu, m, d));
        vlab = fmaxf(vlab, __shfl_xor_sync(0xffffffffu, vlab, d));
    }
    float e = 0.f;
    #pragma unroll
    for (int k = 0; k < 8; k++)
        e += __expf(v[k].x - m) + __expf(v[k].y - m)
           + __expf(v[k].z - m) + __expf(v[k].w - m);
    #pragma unroll
    for (int d = 16; d; d >>= 1) e += __shfl_xor_sync(0xffffffffu, e, d);
    if (l == 0) g_ce[i] = -(vlab - m - logf(e));

    float4 f  = ((const float4*)(g_featn  + (size_t)i   * DN))[l];
    float4 mm = ((const float4*)(g_meansn + (size_t)lab * DN))[l];
    float dx = f.x - mm.x, dy = f.y - mm.y, dz = f.z - mm.z, dw = f.w - mm.w;
    float ms = dx * dx + dy * dy + dz * dz + dw * dw;
    #pragma unroll
    for (int d = 16; d; d >>= 1) ms += __shfl_xor_sync(0xffffffffu, ms, d);
    if (l == 0) g_margin[i] = ms;
}

// ---------------- SCL: bottom-only, mask-free fused GEMM + row reduction -----
// CTA = 256 i-rows x 128 j-cols; 8 warps x 32 rows -> 4 HMMA per B LDSM.x4.
// Self-term included here; combine subtracts exp(f_i.f_i/T).
__global__ void __launch_bounds__(256, 2) scl_mma_kernel() {
    extern __shared__ __align__(16) char sm[];
    char* smT = sm;

    int tid = threadIdx.x;
    int w = tid >> 5;
    int l = tid & 31;
    int ib = blockIdx.x * 256;
    int split = blockIdx.y;

    uint32_t a[2][8][4];   // [strip 0/1][k-step][frag]

    // half 0 (rows ib..ib+127): warps 0-3 extract their 2 strips
    load_tile(smT, g_featbH, ib, tid);
    __syncthreads();
    if (w < 4) {
        uint32_t base = smem_u32(smT);
        load_a_frags16(base, 32 * w,      l, a[0]);
        load_a_frags16(base, 32 * w + 16, l, a[1]);
    }
    __syncthreads();
    // half 1 (rows ib+128..ib+255): warps 4-7 extract
    load_tile(smT, g_featbH, ib + 128, tid);
    __syncthreads();
    if (w >= 4) {
        uint32_t base = smem_u32(smT);
        load_a_frags16(base, 32 * (w - 4),      l, a[0]);
        load_a_frags16(base, 32 * (w - 4) + 16, l, a[1]);
    }

    // ex2(x * C2) == expf(x / T):  C2 = log2(e)/0.3
    const float C2 = 4.80898346963f;
    float sB[4] = {0.f, 0.f, 0.f, 0.f};

    uint32_t bbase = smem_u32(smT);
    uint32_t brow = (l & 7);
    uint32_t bkoff = 8 * (l >> 3);

    for (int jt = 0; jt < 64 / TSPLIT; jt++) {
        int jb = (split * (64 / TSPLIT) + jt) * 128;

        __syncthreads();   // previous tile (or A extraction) fully consumed
        load_tile(smT, g_featbH, jb, tid);
        __syncthreads();

        #pragma unroll
        for (int nb = 0; nb < 16; nb++) {
            float e0[4] = {0.f, 0.f, 0.f, 0.f}, o0[4] = {0.f, 0.f, 0.f, 0.f};
            float e1[4] = {0.f, 0.f, 0.f, 0.f}, o1[4] = {0.f, 0.f, 0.f, 0.f};
            #pragma unroll
            for (int kp = 0; kp < 4; kp++) {
                uint32_t b[4];
                LDSM4(b, bbase + (nb * 8 + brow) * STRIDE + (32 * kp + bkoff) * 2);
                HMMA4(e0, a[0][2 * kp],     b[0], b[1]);
                HMMA4(e1, a[1][2 * kp],     b[0], b[1]);
                HMMA4(o0, a[0][2 * kp + 1], b[2], b[3]);
                HMMA4(o1, a[1][2 * kp + 1], b[2], b[3]);
            }
            sB[0] += ex2((e0[0] + o0[0]) * C2) + ex2((e0[1] + o0[1]) * C2);
            sB[1] += ex2((e0[2] + o0[2]) * C2) + ex2((e0[3] + o0[3]) * C2);
            sB[2] += ex2((e1[0] + o1[0]) * C2) + ex2((e1[1] + o1[1]) * C2);
            sB[3] += ex2((e1[2] + o1[2]) * C2) + ex2((e1[3] + o1[3]) * C2);
        }
    }

    // deterministic reduce across the 4 lanes sharing each row
    #pragma unroll
    for (int q = 0; q < 4; q++) {
        #pragma unroll
        for (int d = 2; d; d >>= 1)
            sB[q] += __shfl_down_sync(0xffffffffu, sB[q], d, 4);
    }
    if ((l & 3) == 0) {
        int base_r = ib + 32 * w + (l >> 2);
        g_pb[split * BN + base_r]      = sB[0];
        g_pb[split * BN + base_r + 8]  = sB[1];
        g_pb[split * BN + base_r + 16] = sB[2];
        g_pb[split * BN + base_r + 24] = sB[3];
    }
}

// ---------------- combine: bottom (minus self) + closed-form positives -------
__global__ void combine_kernel() {
    int i = blockIdx.x * 256 + threadIdx.x;
    float bsum = 0.f;
    #pragma unroll
    for (int s = 0; s < TSPLIT; s++) bsum += g_pb[s * BN + i];

    int lab = g_lab[i];
    int cnt = g_cnt[lab] - 1;

    const float* fi = g_featn + (size_t)i * DN;
    const float* sc = g_S + (size_t)lab * DN;
    float dotS = 0.f, dotSelf = 0.f;
    #pragma unroll 8
    for (int k = 0; k < DN / 4; k++) {
        float4 f = ((const float4*)fi)[k];
        float4 s4 = ((const float4*)sc)[k];
        dotS += f.x * s4.x + f.y * s4.y + f.z * s4.z + f.w * s4.w;
        dotSelf += f.x * f.x + f.y * f.y + f.z * f.z + f.w * f.w;
    }
    const float invT = 1.0f / 0.3f;
    const float C2 = 4.80898346963f;
    float bottom = bsum - ex2(dotSelf * C2);   // remove self-term (same EX2 path as scl)
    float pp = (dotS - dotSelf) * invT;

    bool valid = (cnt > 0);
    g_peri[i]  = valid ? (pp / (float)cnt - logf(bottom)) : 0.f;
    g_valid[i] = valid ? 1.f : 0.f;
}

__global__ void final_kernel(float* __restrict__ out, long long scalar_idx) {
    int t = threadIdx.x;
    float sp = 0.f, sv = 0.f, sc = 0.f, smg = 0.f;
    for (int i = t; i < BN; i += 256) {
        sp += g_peri[i];
        sv += g_valid[i];
        sc += g_ce[i];
        smg += g_margin[i];
    }
    __shared__ float r0[256], r1[256], r2[256], r3[256];
    r0[t] = sp; r1[t] = sv; r2[t] = sc; r3[t] = smg;
    __syncthreads();
    for (int d = 128; d; d >>= 1) {
        if (t < d) { r0[t] += r0[t+d]; r1[t] += r1[t+d]; r2[t] += r2[t+d]; r3[t] += r3[t+d]; }
        __syncthreads();
    }
    if (t == 0) {
        float scl = -r0[0] / fmaxf(r1[0], 1.f);
        float ce  = r2[0] / (float)BN;
        float lm  = r3[0] / (2.f * (float)BN);
        out[scalar_idx] = 0.9f * ce + 0.1f * scl + 0.5f * lm;
    }
}

// ---------------- launch ------------------------------------------------------
extern "C" void kernel_launch(void* const* d_in, const int* in_sizes, int n_in,
                              void* d_out, int out_size) {
    const float* feat   = (const float*)d_in[0];
    const int*   labels = (const int*)d_in[1];
    const float* means  = (const float*)d_in[2];
    float* out = (float*)d_out;

    static cudaStream_t sB = nullptr;
    static cudaEvent_t  eF = nullptr, eJ = nullptr;
    static int initTried = 0;
    if (!initTried) {
        initTried = 1;
        if (cudaStreamCreateWithFlags(&sB, cudaStreamNonBlocking) != cudaSuccess) sB = nullptr;
        if (sB) {
            if (cudaEventCreateWithFlags(&eF, cudaEventDisableTiming) != cudaSuccess) { eF = nullptr; }
            if (cudaEventCreateWithFlags(&eJ, cudaEventDisableTiming) != cudaSuccess) { eJ = nullptr; }
            if (!eF || !eJ) sB = nullptr;
        }
        cudaFuncSetAttribute(nsd_mma_kernel, cudaFuncAttributeMaxDynamicSharedMemorySize, SMEM_NSD);
        cudaFuncSetAttribute(scl_mma_kernel, cudaFuncAttributeMaxDynamicSharedMemorySize, SMEM_SCL);
    }
    bool fork = (sB != nullptr);

    prep_feat_kernel<<<BN / 8, dim3(32, 8)>>>(feat, labels);

    if (fork) {
        cudaEventRecord(eF, 0);
        cudaStreamWaitEvent(sB, eF, 0);
        scl_mma_kernel<<<dim3(BN / 256, TSPLIT), 256, SMEM_SCL, sB>>>();
        cudaEventRecord(eJ, sB);
    }

    prep_means_kernel<<<CPAD / 8, dim3(32, 8)>>>(means);
    nsd_mma_kernel<<<dim3(BN / 128, CPAD / 128), 256, SMEM_NSD>>>(out);
    ce_kernel<<<BN / 8, 256>>>(out);
    class_sum_kernel<<<CN / 8, 256>>>();

    if (fork) {
        cudaStreamWaitEvent(0, eJ, 0);
    } else {
        scl_mma_kernel<<<dim3(BN / 256, TSPLIT), 256, SMEM_SCL>>>();
    }

    combine_kernel<<<BN / 256, 256>>>();
    final_kernel<<<1, 256>>>(out, (long long)out_size - 1);
}